// round 10
// baseline (speedup 1.0000x reference)
#include <cuda_runtime.h>
#include <stdint.h>
#include <math.h>

// ---------------------------------------------------------------------------
// DetectionTargetLayer (Mask R-CNN) — exact replication of the JAX reference.
// R10: ONE kernel, ONE graph node, NO grid sync. Each block independently
// recomputes the (deterministic) positive selection it needs:
//   blocks 0..399  : one output ROI row each (mask crop or zeros)
//   blocks 400..401: rois/class_ids/deltas for image b = blk-400
// Blocks with j >= PCAP never score (always zero). FP paths byte-identical
// to the passing R8 kernel.
// ---------------------------------------------------------------------------

#define JAX_PARTITIONABLE 1

#define BB     2
#define NPROP  2000
#define NGT    50
#define TRAIN  200
#define PCAP   66
#define NCAP   134
#define MH     28
#define MW     28
#define IMH    1024
#define IMW    1024
#define SORTN  2048
#define POSK_CAP 128
#define NEGK_CAP 512
#define NEG_THR  0.85f

#define NBLK_MASK (BB * TRAIN)          // 400
#define GRID_ALL  (NBLK_MASK + BB)      // 402
#define BT 256

#define ROIS_OFF 0
#define CLS_OFF  (BB*TRAIN*4)
#define DELT_OFF (CLS_OFF + BB*TRAIN)
#define MASK_OFF (DELT_OFF + BB*TRAIN*4)

#define NEG_RATIO_F ((float)(1.0/0.33))   // np.float32(1.0/ROI_POS_RATIO)
#define STEPC (1023.0f / 27.0f)           // folded constant rn(1023/27)

struct Keys { uint32_t kp0[BB], kp1[BB], kn0[BB], kn1[BB]; };

__host__ __device__ __forceinline__ uint32_t rotl32(uint32_t v, int r) {
    return (v << r) | (v >> (32 - r));
}

__host__ __device__ __forceinline__ void threefry2x32(
    uint32_t k0, uint32_t k1, uint32_t x0, uint32_t x1,
    uint32_t* o0, uint32_t* o1)
{
    uint32_t ks2 = k0 ^ k1 ^ 0x1BD11BDAu;
    x0 += k0; x1 += k1;
#define TF_R(r) { x0 += x1; x1 = rotl32(x1, (r)); x1 ^= x0; }
    TF_R(13) TF_R(15) TF_R(26) TF_R(6)   x0 += k1;  x1 += ks2 + 1u;
    TF_R(17) TF_R(29) TF_R(16) TF_R(24)  x0 += ks2; x1 += k0 + 2u;
    TF_R(13) TF_R(15) TF_R(26) TF_R(6)   x0 += k0;  x1 += k1 + 3u;
    TF_R(17) TF_R(29) TF_R(16) TF_R(24)  x0 += k1;  x1 += ks2 + 4u;
    TF_R(13) TF_R(15) TF_R(26) TF_R(6)   x0 += ks2; x1 += k0 + 5u;
#undef TF_R
    *o0 = x0; *o1 = x1;
}

__device__ __forceinline__ float bits_to_uniform(uint32_t bits) {
    return __uint_as_float((bits >> 9) | 0x3f800000u) - 1.0f;
}

__device__ __forceinline__ float uniform_at(uint32_t k0, uint32_t k1, int i) {
#if JAX_PARTITIONABLE
    uint32_t o0, o1;
    threefry2x32(k0, k1, 0u, (uint32_t)i, &o0, &o1);
    return bits_to_uniform(o0 ^ o1);
#else
    uint32_t o0, o1;
    if (i < NPROP / 2) {
        threefry2x32(k0, k1, (uint32_t)i, (uint32_t)(i + NPROP / 2), &o0, &o1);
        return bits_to_uniform(o0);
    } else {
        threefry2x32(k0, k1, (uint32_t)(i - NPROP / 2), (uint32_t)i, &o0, &o1);
        return bits_to_uniform(o1);
    }
#endif
}

// Exact IoU (argmax/deltas path — matches reference arithmetic).
__device__ __forceinline__ float iou_f(
    float ay1, float ax1, float ay2, float ax2,
    float by1, float bx1, float by2, float bx2)
{
    float ih = fmaxf(fminf(ay2, by2) - fmaxf(ay1, by1), 0.0f);
    float iw = fmaxf(fminf(ax2, bx2) - fmaxf(ax1, bx1), 0.0f);
    float inter = __fmul_rn(ih, iw);
    float a1 = __fmul_rn(ay2 - ay1, ax2 - ax1);
    float a2 = __fmul_rn(by2 - by1, bx2 - bx1);
    float uni = (a1 + a2) - inter;
    return (uni > 0.0f) ? __fdiv_rn(inter, uni) : 0.0f;
}

// Division-free intersection/union (classification path).
__device__ __forceinline__ void iou_parts(
    float ay1, float ax1, float ay2, float ax2,
    float by1, float bx1, float by2, float bx2,
    float* inter_o, float* uni_o)
{
    float ih = fmaxf(fminf(ay2, by2) - fmaxf(ay1, by1), 0.0f);
    float iw = fmaxf(fminf(ax2, bx2) - fmaxf(ax1, bx1), 0.0f);
    float inter = __fmul_rn(ih, iw);
    float a1 = __fmul_rn(ay2 - ay1, ax2 - ax1);
    float a2 = __fmul_rn(by2 - by1, bx2 - bx1);
    *inter_o = inter;
    *uni_o = (a1 + a2) - inter;
}

// Division-free classification of one proposal (validated bit-exact R7/R8).
__device__ __forceinline__ void classify_prop(
    float py1, float px1, float py2, float px2,
    const float (*gt)[4], const int* ncf, const int* crf,
    bool* pos_o, bool* neg_o)
{
    bool valid = (fabsf(py1) + fabsf(px1) + fabsf(py2) + fabsf(px2)) > 0.0f;
    bool any_pos = false, any_crowd = false;
    #pragma unroll 5
    for (int g = 0; g < NGT; ++g) {
        float inter, uni;
        iou_parts(py1, px1, py2, px2,
                  gt[g][0], gt[g][1], gt[g][2], gt[g][3], &inter, &uni);
        bool pos_g = (uni > 0.0f) && (inter >= __fmul_rn(0.5f, uni));
        bool cr_g  = (uni > 0.0f) && (inter >= __fmul_rn(1e-3f, uni));
        if (ncf[g] && pos_g) any_pos = true;
        if (crf[g] && cr_g)  any_crowd = true;
    }
    *pos_o = valid && any_pos;
    *neg_o = valid && !any_pos && !any_crowd;
}

// Map float -> uint32 such that ascending uint = DESCENDING float.
__device__ __forceinline__ uint32_t desc_map(float f) {
    uint32_t u = __float_as_uint(f);
    uint32_t m = (u & 0x80000000u) ? ~u : (u | 0x80000000u);
    return ~m;
}
__device__ __forceinline__ unsigned long long mk_key(float f, int idx) {
    return ((unsigned long long)desc_map(f) << 32) | (uint32_t)idx;
}

// Ascending bitonic sort of SZ u64 keys in shared (SZ power of 2).
__device__ __forceinline__ void bitonic_sort_u64(unsigned long long* key, int SZ) {
    for (int k = 2; k <= SZ; k <<= 1) {
        for (int j = k >> 1; j > 0; j >>= 1) {
            __syncthreads();
            for (int t = threadIdx.x; t < SZ; t += blockDim.x) {
                int l = t ^ j;
                if (l > t) {
                    unsigned long long a = key[t], bk = key[l];
                    bool up = ((t & k) == 0);
                    if ((a > bk) == up) { key[t] = bk; key[l] = a; }
                }
            }
        }
    }
    __syncthreads();
}

// ---------------------------------------------------------------------------
__global__ __launch_bounds__(BT)
void dtl_all(const float* __restrict__ proposals,
             const int*   __restrict__ gt_class_ids,
             const float* __restrict__ gt_boxes,
             const float* __restrict__ gt_masks,
             float* __restrict__ out,
             Keys keys)
{
    const int blk = blockIdx.x;
    const int tid = threadIdx.x;
    const bool is_select = (blk >= NBLK_MASK);
    const int b = is_select ? (blk - NBLK_MASK) : (blk / TRAIN);
    const int j = is_select ? 0 : (blk % TRAIN);

    // Mask rows that can never be positive (p <= PCAP): pure zero-fill.
    if (!is_select && j >= PCAP) {
        float* mo = out + MASK_OFF + (size_t)blk * (MH * MW);
        for (int t = tid; t < MH * MW; t += BT) mo[t] = 0.0f;
        return;
    }

    __shared__ float s_gt[NGT][4];
    __shared__ int   s_cls[NGT];
    __shared__ int   s_noncrowd[NGT];
    __shared__ int   s_crowd[NGT];
    __shared__ unsigned long long posk[POSK_CAP];
    __shared__ unsigned long long negk[NEGK_CAP];
    __shared__ unsigned long long bigk[SORTN];   // fallback only
    __shared__ int s_np, s_nthr, s_cneg;
    __shared__ float s_ov[NGT];
    __shared__ int s_a;

    if (tid == 0) { s_np = 0; s_nthr = 0; s_cneg = 0; }
    if (tid < NGT) {
        float g0 = gt_boxes[((size_t)b * NGT + tid) * 4 + 0];
        float g1 = gt_boxes[((size_t)b * NGT + tid) * 4 + 1];
        float g2 = gt_boxes[((size_t)b * NGT + tid) * 4 + 2];
        float g3 = gt_boxes[((size_t)b * NGT + tid) * 4 + 3];
        s_gt[tid][0] = g0; s_gt[tid][1] = g1; s_gt[tid][2] = g2; s_gt[tid][3] = g3;
        int valid = (fabsf(g0) + fabsf(g1) + fabsf(g2) + fabsf(g3)) > 0.0f;
        int cls = gt_class_ids[(size_t)b * NGT + tid];
        s_cls[tid] = cls;
        s_noncrowd[tid] = (cls > 0) && valid;
        s_crowd[tid]    = (cls < 0) && valid;
    }
    __syncthreads();

    // -------- scoring pass (division-free) --------------------------------
    for (int i = tid; i < NPROP; i += BT) {
        const float* pr = proposals + ((size_t)b * NPROP + i) * 4;
        float py1 = pr[0], px1 = pr[1], py2 = pr[2], px2 = pr[3];
        bool pos, neg;
        classify_prop(py1, px1, py2, px2, s_gt, s_noncrowd, s_crowd, &pos, &neg);
        if (pos) {
            float ps = uniform_at(keys.kp0[b], keys.kp1[b], i);
            int slot = atomicAdd(&s_np, 1);
            if (slot < POSK_CAP) posk[slot] = mk_key(ps, i);
        }
        if (is_select && neg) {
            atomicAdd(&s_cneg, 1);
            float ns = uniform_at(keys.kn0[b], keys.kn1[b], i);
            if (ns > NEG_THR) {
                int slot = atomicAdd(&s_nthr, 1);
                if (slot < NEGK_CAP) negk[slot] = mk_key(ns, i);
            }
        }
    }
    __syncthreads();

    const int np_total = s_np;
    const int p = min(np_total, PCAP);

    // -------- positive top-k (sort canonicalizes atomic order) -----------
    const unsigned long long* psorted;
    if (np_total <= POSK_CAP) {
        for (int t = tid; t < POSK_CAP; t += BT)
            if (t >= np_total) posk[t] = 0xFFFFFFFFFFFFFFFFull;
        __syncthreads();
        bitonic_sort_u64(posk, POSK_CAP);
        psorted = posk;
    } else {
        // fallback: recompute all positive scores, full sort (never hit here)
        for (int t = tid; t < SORTN; t += BT) {
            unsigned long long key = 0xFFFFFFFFFFFFFFFFull;
            if (t < NPROP) {
                const float* pr = proposals + ((size_t)b * NPROP + t) * 4;
                bool pos, neg;
                classify_prop(pr[0], pr[1], pr[2], pr[3],
                              s_gt, s_noncrowd, s_crowd, &pos, &neg);
                float ps = pos ? uniform_at(keys.kp0[b], keys.kp1[b], t) : -1.0f;
                key = mk_key(ps, t);
            }
            bigk[t] = key;
        }
        __syncthreads();
        bitonic_sort_u64(bigk, SORTN);
        psorted = bigk;
    }

    // =====================================================================
    if (!is_select) {
        // ---------------- mask block: one output ROI row -----------------
        float* mo = out + MASK_OFF + (size_t)blk * (MH * MW);
        if (j >= p) {
            for (int t = tid; t < MH * MW; t += BT) mo[t] = 0.0f;
            return;
        }
        const int i = (int)(uint32_t)psorted[j];
        const float* pr = proposals + ((size_t)b * NPROP + i) * 4;
        const float y1 = pr[0], x1 = pr[1], y2 = pr[2], x2 = pr[3];

        // argmax (reference order: first max) — parallel eval, serial reduce
        if (tid < NGT) {
            s_ov[tid] = s_noncrowd[tid]
                      ? iou_f(y1, x1, y2, x2,
                              s_gt[tid][0], s_gt[tid][1], s_gt[tid][2], s_gt[tid][3])
                      : -1.0f;
        }
        __syncthreads();
        if (tid == 0) {
            int a = 0; float best = -1.0f;
            for (int g = 0; g < NGT; ++g)
                if (s_ov[g] > best) { best = s_ov[g]; a = g; }
            s_a = a;
        }
        __syncthreads();
        const int g = s_a;

        for (int pix = tid; pix < MH * MW; pix += BT) {
            const int r = pix / MW, c = pix % MW;

            float ybase = __fmul_rn(y1, 1023.0f);
            float ystep = __fmul_rn(y2 - y1, STEPC);
            float fy    = __fadd_rn(ybase, __fmul_rn((float)r, ystep));
            float yf0 = floorf(fy);
            float wy  = fy - yf0;
            int y0i = (int)fminf(fmaxf(yf0, 0.0f), 1023.0f);
            int y1i = (int)fminf(fmaxf(yf0 + 1.0f, 0.0f), 1023.0f);
            bool vy = (fy >= 0.0f) && (fy <= 1023.0f);

            float xbase = __fmul_rn(x1, 1023.0f);
            float xstep = __fmul_rn(x2 - x1, STEPC);
            float fx    = __fadd_rn(xbase, __fmul_rn((float)c, xstep));
            float xf0 = floorf(fx);
            float wx  = fx - xf0;
            int x0i = (int)fminf(fmaxf(xf0, 0.0f), 1023.0f);
            int x1i = (int)fminf(fmaxf(xf0 + 1.0f, 0.0f), 1023.0f);
            bool vx = (fx >= 0.0f) && (fx <= 1023.0f);

            if (!(vy && vx)) { mo[pix] = 0.0f; continue; }

            size_t rb0 = ((size_t)(b * IMH + y0i)) * IMW;
            size_t rb1 = ((size_t)(b * IMH + y1i)) * IMW;
            float m00 = __ldg(&gt_masks[(rb0 + x0i) * NGT + g]);
            float m01 = __ldg(&gt_masks[(rb0 + x1i) * NGT + g]);
            float m10 = __ldg(&gt_masks[(rb1 + x0i) * NGT + g]);
            float m11 = __ldg(&gt_masks[(rb1 + x1i) * NGT + g]);
            float omwx = 1.0f - wx, omwy = 1.0f - wy;
            float top = __fadd_rn(__fmul_rn(m00, omwx), __fmul_rn(m01, wx));
            float bot = __fadd_rn(__fmul_rn(m10, omwx), __fmul_rn(m11, wx));
            float v   = __fadd_rn(__fmul_rn(top, omwy), __fmul_rn(bot, wy));
            mo[pix] = rintf(v);   // round half to even
        }
        return;
    }

    // ---------------- select block: rois / class / deltas ----------------
    const int nthr = s_nthr;
    const int cneg = s_cneg;
    const int needed = (int)(NEG_RATIO_F * (float)p) - p;
    const int n = min(min(cneg, needed), NCAP);

    unsigned long long my_pos_key = (tid < PCAP) ? psorted[tid] : 0;
    __syncthreads();

    const unsigned long long* nsorted;
    if (nthr >= n && nthr <= NEGK_CAP) {
        for (int t = tid; t < NEGK_CAP; t += BT)
            if (t >= nthr) negk[t] = 0xFFFFFFFFFFFFFFFFull;
        __syncthreads();
        bitonic_sort_u64(negk, NEGK_CAP);
        nsorted = negk;
    } else {
        // fallback: recompute all negative scores, full sort (never hit here)
        for (int t = tid; t < SORTN; t += BT) {
            unsigned long long key = 0xFFFFFFFFFFFFFFFFull;
            if (t < NPROP) {
                const float* pr = proposals + ((size_t)b * NPROP + t) * 4;
                bool pos, neg;
                classify_prop(pr[0], pr[1], pr[2], pr[3],
                              s_gt, s_noncrowd, s_crowd, &pos, &neg);
                float ns = neg ? uniform_at(keys.kn0[b], keys.kn1[b], t) : -1.0f;
                key = mk_key(ns, t);
            }
            bigk[t] = key;
        }
        __syncthreads();
        bitonic_sort_u64(bigk, SORTN);
        nsorted = bigk;
    }

    float* rois_o = out + ROIS_OFF + (size_t)b * TRAIN * 4;
    float* cls_o  = out + CLS_OFF  + (size_t)b * TRAIN;
    float* del_o  = out + DELT_OFF + (size_t)b * TRAIN * 4;

    for (int t = tid; t < TRAIN * 4; t += BT) { rois_o[t] = 0.0f; del_o[t] = 0.0f; }
    for (int t = tid; t < TRAIN;     t += BT) { cls_o[t] = 0.0f; }

    // positives
    if (tid < PCAP && tid < p) {
        const int jj = tid;
        int i = (int)(uint32_t)my_pos_key;
        const float* pr = proposals + ((size_t)b * NPROP + i) * 4;
        float ry1 = pr[0], rx1 = pr[1], ry2 = pr[2], rx2 = pr[3];

        int a = 0; float best = -1.0f;
        for (int g = 0; g < NGT; ++g) {
            float ov = s_noncrowd[g]
                     ? iou_f(ry1, rx1, ry2, rx2,
                             s_gt[g][0], s_gt[g][1], s_gt[g][2], s_gt[g][3])
                     : -1.0f;
            if (ov > best) { best = ov; a = g; }
        }

        rois_o[jj * 4 + 0] = ry1; rois_o[jj * 4 + 1] = rx1;
        rois_o[jj * 4 + 2] = ry2; rois_o[jj * 4 + 3] = rx2;

        float h  = ry2 - ry1,  w  = rx2 - rx1;
        float cy = ry1 + 0.5f * h, cx = rx1 + 0.5f * w;
        float gy1 = s_gt[a][0], gx1 = s_gt[a][1], gy2 = s_gt[a][2], gx2 = s_gt[a][3];
        float gh = gy2 - gy1, gw = gx2 - gx1;
        float gcy = gy1 + 0.5f * gh, gcx = gx1 + 0.5f * gw;
        del_o[jj * 4 + 0] = __fmul_rn(__fdiv_rn(gcy - cy, h), 10.0f);
        del_o[jj * 4 + 1] = __fmul_rn(__fdiv_rn(gcx - cx, w), 10.0f);
        del_o[jj * 4 + 2] = __fmul_rn(logf(__fdiv_rn(gh, h)), 5.0f);
        del_o[jj * 4 + 3] = __fmul_rn(logf(__fdiv_rn(gw, w)), 5.0f);

        cls_o[jj] = (float)s_cls[a];
    }

    // negatives: rois rows [p, p+n)
    if (tid >= PCAP && tid < PCAP + NCAP) {
        const int jj = tid - PCAP;
        if (jj < n) {
            int i = (int)(uint32_t)nsorted[jj];
            const float* pr = proposals + ((size_t)b * NPROP + i) * 4;
            const int row = p + jj;
            rois_o[row * 4 + 0] = pr[0]; rois_o[row * 4 + 1] = pr[1];
            rois_o[row * 4 + 2] = pr[2]; rois_o[row * 4 + 3] = pr[3];
        }
    }
}

// ---------------------------------------------------------------------------
static void compute_keys(Keys* K) {
#if JAX_PARTITIONABLE
    for (int b = 0; b < BB; b++) {
        uint32_t kb0, kb1;
        threefry2x32(0u, 42u, 0u, (uint32_t)b, &kb0, &kb1);
        threefry2x32(kb0, kb1, 0u, 0u, &K->kp0[b], &K->kp1[b]);
        threefry2x32(kb0, kb1, 0u, 1u, &K->kn0[b], &K->kn1[b]);
    }
#else
    uint32_t a0, b0, a1, b1;
    threefry2x32(0u, 42u, 0u, 2u, &a0, &b0);
    threefry2x32(0u, 42u, 1u, 3u, &a1, &b1);
    uint32_t kb[BB][2] = { { a0, a1 }, { b0, b1 } };
    for (int b = 0; b < BB; b++) {
        uint32_t c0, d0, c1, d1;
        threefry2x32(kb[b][0], kb[b][1], 0u, 2u, &c0, &d0);
        threefry2x32(kb[b][0], kb[b][1], 1u, 3u, &c1, &d1);
        K->kp0[b] = c0; K->kp1[b] = c1;
        K->kn0[b] = d0; K->kn1[b] = d1;
    }
#endif
}

extern "C" void kernel_launch(void* const* d_in, const int* in_sizes, int n_in,
                              void* d_out, int out_size)
{
    const float* proposals    = (const float*)d_in[0];
    const int*   gt_class_ids = (const int*)d_in[1];
    const float* gt_boxes     = (const float*)d_in[2];
    const float* gt_masks     = (const float*)d_in[3];
    float* out = (float*)d_out;

    Keys keys;
    compute_keys(&keys);

    dtl_all<<<GRID_ALL, BT>>>(proposals, gt_class_ids, gt_boxes, gt_masks,
                              out, keys);
}

// round 11
// speedup vs baseline: 2.3324x; 2.3324x over previous
#include <cuda_runtime.h>
#include <stdint.h>
#include <math.h>

// ---------------------------------------------------------------------------
// DetectionTargetLayer (Mask R-CNN) — exact replication of the JAX reference.
// R11: R8 two-kernel topology (the measured optimum) with:
//   - compact GT lists + hoisted areas in classification (order-free ORs)
//   - warp-reduced negative counting (1 atomic/warp)
//   - concurrent pos/neg bitonic sorts via named barriers
//   - 2-pixel-per-thread mask kernel (double MLP)
//   - fixed zero-fill/write race with an explicit __syncthreads
// All FP output paths byte-identical to the passing R8 kernel.
// ---------------------------------------------------------------------------

#define JAX_PARTITIONABLE 1

#define BB     2
#define NPROP  2000
#define NGT    50
#define TRAIN  200
#define PCAP   66
#define NCAP   134
#define MH     28
#define MW     28
#define IMH    1024
#define IMW    1024
#define SORTN  2048
#define POSK_CAP 128
#define NEGK_CAP 512
#define NEG_THR  0.85f

#define ROIS_OFF 0
#define CLS_OFF  (BB*TRAIN*4)
#define DELT_OFF (CLS_OFF + BB*TRAIN)
#define MASK_OFF (DELT_OFF + BB*TRAIN*4)

#define NEG_RATIO_F ((float)(1.0/0.33))   // np.float32(1.0/ROI_POS_RATIO)
#define STEPC (1023.0f / 27.0f)           // folded constant rn(1023/27)

struct Keys { uint32_t kp0[BB], kp1[BB], kn0[BB], kn1[BB]; };

__host__ __device__ __forceinline__ uint32_t rotl32(uint32_t v, int r) {
    return (v << r) | (v >> (32 - r));
}

__host__ __device__ __forceinline__ void threefry2x32(
    uint32_t k0, uint32_t k1, uint32_t x0, uint32_t x1,
    uint32_t* o0, uint32_t* o1)
{
    uint32_t ks2 = k0 ^ k1 ^ 0x1BD11BDAu;
    x0 += k0; x1 += k1;
#define TF_R(r) { x0 += x1; x1 = rotl32(x1, (r)); x1 ^= x0; }
    TF_R(13) TF_R(15) TF_R(26) TF_R(6)   x0 += k1;  x1 += ks2 + 1u;
    TF_R(17) TF_R(29) TF_R(16) TF_R(24)  x0 += ks2; x1 += k0 + 2u;
    TF_R(13) TF_R(15) TF_R(26) TF_R(6)   x0 += k0;  x1 += k1 + 3u;
    TF_R(17) TF_R(29) TF_R(16) TF_R(24)  x0 += k1;  x1 += ks2 + 4u;
    TF_R(13) TF_R(15) TF_R(26) TF_R(6)   x0 += ks2; x1 += k0 + 5u;
#undef TF_R
    *o0 = x0; *o1 = x1;
}

__device__ __forceinline__ float bits_to_uniform(uint32_t bits) {
    return __uint_as_float((bits >> 9) | 0x3f800000u) - 1.0f;
}

__device__ __forceinline__ float uniform_at(uint32_t k0, uint32_t k1, int i) {
#if JAX_PARTITIONABLE
    uint32_t o0, o1;
    threefry2x32(k0, k1, 0u, (uint32_t)i, &o0, &o1);
    return bits_to_uniform(o0 ^ o1);
#else
    uint32_t o0, o1;
    if (i < NPROP / 2) {
        threefry2x32(k0, k1, (uint32_t)i, (uint32_t)(i + NPROP / 2), &o0, &o1);
        return bits_to_uniform(o0);
    } else {
        threefry2x32(k0, k1, (uint32_t)(i - NPROP / 2), (uint32_t)i, &o0, &o1);
        return bits_to_uniform(o1);
    }
#endif
}

// Exact IoU (argmax/deltas path — matches reference arithmetic).
__device__ __forceinline__ float iou_f(
    float ay1, float ax1, float ay2, float ax2,
    float by1, float bx1, float by2, float bx2)
{
    float ih = fmaxf(fminf(ay2, by2) - fmaxf(ay1, by1), 0.0f);
    float iw = fmaxf(fminf(ax2, bx2) - fmaxf(ax1, bx1), 0.0f);
    float inter = __fmul_rn(ih, iw);
    float a1 = __fmul_rn(ay2 - ay1, ax2 - ax1);
    float a2 = __fmul_rn(by2 - by1, bx2 - bx1);
    float uni = (a1 + a2) - inter;
    return (uni > 0.0f) ? __fdiv_rn(inter, uni) : 0.0f;
}

// Map float -> uint32 such that ascending uint = DESCENDING float.
__device__ __forceinline__ uint32_t desc_map(float f) {
    uint32_t u = __float_as_uint(f);
    uint32_t m = (u & 0x80000000u) ? ~u : (u | 0x80000000u);
    return ~m;
}
__device__ __forceinline__ unsigned long long mk_key(float f, int idx) {
    return ((unsigned long long)desc_map(f) << 32) | (uint32_t)idx;
}

// staging between kernels
__device__ float g_pos_rois[BB][PCAP][4];
__device__ int   g_assign[BB][PCAP];
__device__ int   g_p[BB];

// Full-block ascending bitonic sort (fallback path).
__device__ __forceinline__ void bitonic_sort_u64(unsigned long long* key, int SZ) {
    for (int k = 2; k <= SZ; k <<= 1) {
        for (int j = k >> 1; j > 0; j >>= 1) {
            __syncthreads();
            for (int t = threadIdx.x; t < SZ; t += blockDim.x) {
                int l = t ^ j;
                if (l > t) {
                    unsigned long long a = key[t], bk = key[l];
                    bool up = ((t & k) == 0);
                    if ((a > bk) == up) { key[t] = bk; key[l] = a; }
                }
            }
        }
    }
    __syncthreads();
}

// Partition ascending bitonic sort: nth threads (local id lt) with named barrier.
__device__ __forceinline__ void bitonic_sort_part(unsigned long long* key, int SZ,
                                                  int lt, int nth, int barid)
{
    for (int k = 2; k <= SZ; k <<= 1) {
        for (int j = k >> 1; j > 0; j >>= 1) {
            asm volatile("bar.sync %0, %1;" :: "r"(barid), "r"(nth) : "memory");
            for (int t = lt; t < SZ; t += nth) {
                int l = t ^ j;
                if (l > t) {
                    unsigned long long a = key[t], bk = key[l];
                    bool up = ((t & k) == 0);
                    if ((a > bk) == up) { key[t] = bk; key[l] = a; }
                }
            }
        }
    }
    asm volatile("bar.sync %0, %1;" :: "r"(barid), "r"(nth) : "memory");
}

// ---------------------------------------------------------------------------
// Kernel 1: scoring + selection + rois/class/deltas. grid BB x 1024.
// ---------------------------------------------------------------------------
__global__ __launch_bounds__(1024)
void dtl_main2(const float* __restrict__ proposals,
               const int*   __restrict__ gt_class_ids,
               const float* __restrict__ gt_boxes,
               float* __restrict__ out,
               Keys keys)
{
    const int b   = blockIdx.x;
    const int tid = threadIdx.x;

    __shared__ float s_gt[NGT][4];
    __shared__ int   s_cls[NGT];
    __shared__ int   s_noncrowd[NGT];
    // compacted classification lists (order-free usage)
    __shared__ float s_nc[NGT][4];
    __shared__ float s_nc_area[NGT];
    __shared__ float s_cr[NGT][4];
    __shared__ float s_cr_area[NGT];
    __shared__ int   s_ncc, s_crc;
    __shared__ float s_pscore[NPROP];
    __shared__ float s_nscore[NPROP];
    __shared__ unsigned long long posk[POSK_CAP];
    __shared__ unsigned long long negk[NEGK_CAP];
    __shared__ unsigned long long bigk[SORTN];   // fallback only
    __shared__ int s_np, s_cneg, s_nthr;

    if (tid == 0) { s_np = 0; s_cneg = 0; s_nthr = 0; s_ncc = 0; s_crc = 0; }
    __syncthreads();
    if (tid < NGT) {
        float g0 = gt_boxes[((size_t)b * NGT + tid) * 4 + 0];
        float g1 = gt_boxes[((size_t)b * NGT + tid) * 4 + 1];
        float g2 = gt_boxes[((size_t)b * NGT + tid) * 4 + 2];
        float g3 = gt_boxes[((size_t)b * NGT + tid) * 4 + 3];
        s_gt[tid][0] = g0; s_gt[tid][1] = g1; s_gt[tid][2] = g2; s_gt[tid][3] = g3;
        int valid = (fabsf(g0) + fabsf(g1) + fabsf(g2) + fabsf(g3)) > 0.0f;
        int cls = gt_class_ids[(size_t)b * NGT + tid];
        s_cls[tid] = cls;
        s_noncrowd[tid] = (cls > 0) && valid;
        float area = __fmul_rn(g2 - g0, g3 - g1);
        if ((cls > 0) && valid) {
            int s = atomicAdd(&s_ncc, 1);
            s_nc[s][0] = g0; s_nc[s][1] = g1; s_nc[s][2] = g2; s_nc[s][3] = g3;
            s_nc_area[s] = area;
        }
        if ((cls < 0) && valid) {
            int s = atomicAdd(&s_crc, 1);
            s_cr[s][0] = g0; s_cr[s][1] = g1; s_cr[s][2] = g2; s_cr[s][3] = g3;
            s_cr_area[s] = area;
        }
    }
    __syncthreads();
    const int ncc = s_ncc, crc = s_crc;

    // -------- phase A: division-free classification + scores -------------
    int my_cneg = 0;
    for (int i = tid; i < NPROP; i += blockDim.x) {
        const float* pr = proposals + ((size_t)b * NPROP + i) * 4;
        float py1 = pr[0], px1 = pr[1], py2 = pr[2], px2 = pr[3];
        bool valid = (fabsf(py1) + fabsf(px1) + fabsf(py2) + fabsf(px2)) > 0.0f;
        float a1 = __fmul_rn(py2 - py1, px2 - px1);
        bool any_pos = false, any_crowd = false;
        #pragma unroll 4
        for (int g = 0; g < ncc; ++g) {
            float ih = fmaxf(fminf(py2, s_nc[g][2]) - fmaxf(py1, s_nc[g][0]), 0.0f);
            float iw = fmaxf(fminf(px2, s_nc[g][3]) - fmaxf(px1, s_nc[g][1]), 0.0f);
            float inter = __fmul_rn(ih, iw);
            float uni = (a1 + s_nc_area[g]) - inter;
            if ((uni > 0.0f) && (inter >= __fmul_rn(0.5f, uni))) any_pos = true;
        }
        for (int g = 0; g < crc; ++g) {
            float ih = fmaxf(fminf(py2, s_cr[g][2]) - fmaxf(py1, s_cr[g][0]), 0.0f);
            float iw = fmaxf(fminf(px2, s_cr[g][3]) - fmaxf(px1, s_cr[g][1]), 0.0f);
            float inter = __fmul_rn(ih, iw);
            float uni = (a1 + s_cr_area[g]) - inter;
            if ((uni > 0.0f) && (inter >= __fmul_rn(1e-3f, uni))) any_crowd = true;
        }
        bool pos = valid && any_pos;
        bool neg = valid && !any_pos && !any_crowd;

        float ps = -1.0f, ns = -1.0f;
        if (pos) {
            ps = uniform_at(keys.kp0[b], keys.kp1[b], i);
            int slot = atomicAdd(&s_np, 1);
            if (slot < POSK_CAP) posk[slot] = mk_key(ps, i);
        }
        if (neg) {
            my_cneg++;
            ns = uniform_at(keys.kn0[b], keys.kn1[b], i);
            if (ns > NEG_THR) {
                int slot = atomicAdd(&s_nthr, 1);
                if (slot < NEGK_CAP) negk[slot] = mk_key(ns, i);
            }
        }
        s_pscore[i] = ps;
        s_nscore[i] = ns;
    }
    {
        int wsum = __reduce_add_sync(0xFFFFFFFFu, my_cneg);
        if ((tid & 31) == 0 && wsum) atomicAdd(&s_cneg, wsum);
    }
    __syncthreads();

    const int np_total = s_np;
    const int cneg     = s_cneg;
    const int nthr     = s_nthr;
    const int p = min(np_total, PCAP);
    const int needed = (int)(NEG_RATIO_F * (float)p) - p;
    const int n = min(min(cneg, needed), NCAP);

    const bool pos_small = (np_total <= POSK_CAP);
    const bool neg_small = (nthr >= n && nthr <= NEGK_CAP);

    unsigned long long my_pos_key = 0;
    const unsigned long long* nsorted;

    if (pos_small && neg_small) {
        // pad both lists, then sort them CONCURRENTLY with named barriers
        if (tid < POSK_CAP && tid >= np_total) posk[tid] = 0xFFFFFFFFFFFFFFFFull;
        if (tid >= 512) {
            int t = tid - 512;
            if (t >= nthr) negk[t] = 0xFFFFFFFFFFFFFFFFull;
        }
        __syncthreads();
        if (tid < 512) bitonic_sort_part(posk, POSK_CAP, tid, 512, 1);
        else           bitonic_sort_part(negk, NEGK_CAP, tid - 512, 512, 2);
        __syncthreads();
        if (tid < PCAP) my_pos_key = posk[tid];
        nsorted = negk;
    } else {
        // sequential fallbacks (never hit for this distribution; kept correct)
        const unsigned long long* psorted;
        if (pos_small) {
            for (int t = tid; t < POSK_CAP; t += blockDim.x)
                if (t >= np_total) posk[t] = 0xFFFFFFFFFFFFFFFFull;
            __syncthreads();
            bitonic_sort_u64(posk, POSK_CAP);
            psorted = posk;
        } else {
            for (int t = tid; t < SORTN; t += blockDim.x)
                bigk[t] = (t < NPROP) ? mk_key(s_pscore[t], t)
                                      : 0xFFFFFFFFFFFFFFFFull;
            __syncthreads();
            bitonic_sort_u64(bigk, SORTN);
            psorted = bigk;
        }
        if (tid < PCAP) my_pos_key = psorted[tid];
        __syncthreads();
        if (neg_small) {
            for (int t = tid; t < NEGK_CAP; t += blockDim.x)
                if (t >= nthr) negk[t] = 0xFFFFFFFFFFFFFFFFull;
            __syncthreads();
            bitonic_sort_u64(negk, NEGK_CAP);
            nsorted = negk;
        } else {
            for (int t = tid; t < SORTN; t += blockDim.x)
                bigk[t] = (t < NPROP) ? mk_key(s_nscore[t], t)
                                      : 0xFFFFFFFFFFFFFFFFull;
            __syncthreads();
            bitonic_sort_u64(bigk, SORTN);
            nsorted = bigk;
        }
    }

    float* rois_o = out + ROIS_OFF + (size_t)b * TRAIN * 4;
    float* cls_o  = out + CLS_OFF  + (size_t)b * TRAIN;
    float* del_o  = out + DELT_OFF + (size_t)b * TRAIN * 4;

    for (int t = tid; t < TRAIN * 4; t += blockDim.x) { rois_o[t] = 0.0f; del_o[t] = 0.0f; }
    for (int t = tid; t < TRAIN;     t += blockDim.x) { cls_o[t] = 0.0f; }
    __syncthreads();   // zero-fill must complete before selected-row writes

    // -------- positives ---------------------------------------------------
    if (tid < PCAP && tid < p) {
        const int j = tid;
        int i = (int)(uint32_t)my_pos_key;
        const float* pr = proposals + ((size_t)b * NPROP + i) * 4;
        float ry1 = pr[0], rx1 = pr[1], ry2 = pr[2], rx2 = pr[3];

        int a = 0; float best = -1.0f;
        for (int g = 0; g < NGT; ++g) {
            float ov = s_noncrowd[g]
                     ? iou_f(ry1, rx1, ry2, rx2,
                             s_gt[g][0], s_gt[g][1], s_gt[g][2], s_gt[g][3])
                     : -1.0f;
            if (ov > best) { best = ov; a = g; }
        }

        rois_o[j * 4 + 0] = ry1; rois_o[j * 4 + 1] = rx1;
        rois_o[j * 4 + 2] = ry2; rois_o[j * 4 + 3] = rx2;

        float h  = ry2 - ry1,  w  = rx2 - rx1;
        float cy = ry1 + 0.5f * h, cx = rx1 + 0.5f * w;
        float gy1 = s_gt[a][0], gx1 = s_gt[a][1], gy2 = s_gt[a][2], gx2 = s_gt[a][3];
        float gh = gy2 - gy1, gw = gx2 - gx1;
        float gcy = gy1 + 0.5f * gh, gcx = gx1 + 0.5f * gw;
        del_o[j * 4 + 0] = __fmul_rn(__fdiv_rn(gcy - cy, h), 10.0f);
        del_o[j * 4 + 1] = __fmul_rn(__fdiv_rn(gcx - cx, w), 10.0f);
        del_o[j * 4 + 2] = __fmul_rn(logf(__fdiv_rn(gh, h)), 5.0f);
        del_o[j * 4 + 3] = __fmul_rn(logf(__fdiv_rn(gw, w)), 5.0f);

        cls_o[j] = (float)s_cls[a];

        g_pos_rois[b][j][0] = ry1; g_pos_rois[b][j][1] = rx1;
        g_pos_rois[b][j][2] = ry2; g_pos_rois[b][j][3] = rx2;
        g_assign[b][j] = a;
    }

    // -------- negatives: rois rows [p, p+n) -------------------------------
    if (tid >= 128 && tid < 128 + NCAP) {
        const int j = tid - 128;
        if (j < n) {
            int i = (int)(uint32_t)nsorted[j];
            const float* pr = proposals + ((size_t)b * NPROP + i) * 4;
            const int row = p + j;
            rois_o[row * 4 + 0] = pr[0]; rois_o[row * 4 + 1] = pr[1];
            rois_o[row * 4 + 2] = pr[2]; rois_o[row * 4 + 3] = pr[3];
        }
    }

    if (tid == 0) g_p[b] = p;
}

// ---------------------------------------------------------------------------
// Kernel 2: masks — TWO pixels per thread (pairs never cross ROI since 784
// is even). Arithmetic byte-identical to the passing version.
// ---------------------------------------------------------------------------
__global__ __launch_bounds__(256)
void dtl_masks2(const float* __restrict__ gt_masks, float* __restrict__ out)
{
    const int tpair = blockIdx.x * 256 + threadIdx.x;
    const int pix0  = tpair * 2;
    if (pix0 >= BB * TRAIN * MH * MW) return;

    const int roi = pix0 / (MH * MW);
    const int b = roi / TRAIN;
    const int j = roi % TRAIN;
    float* mo = out + MASK_OFF + pix0;

    if (j >= g_p[b]) { mo[0] = 0.0f; mo[1] = 0.0f; return; }

    const float y1 = g_pos_rois[b][j][0], x1 = g_pos_rois[b][j][1];
    const float y2 = g_pos_rois[b][j][2], x2 = g_pos_rois[b][j][3];
    const int g = g_assign[b][j];

    const float ybase = __fmul_rn(y1, 1023.0f);
    const float ystep = __fmul_rn(y2 - y1, STEPC);
    const float xbase = __fmul_rn(x1, 1023.0f);
    const float xstep = __fmul_rn(x2 - x1, STEPC);

    bool   vv[2];
    size_t ra0[2], ra1[2];
    int    xx0[2], xx1[2];
    float  wxx[2], wyy[2];

    #pragma unroll
    for (int k = 0; k < 2; ++k) {
        int pix = (pix0 + k) % (MH * MW);
        int r = pix / MW, c = pix % MW;

        float fy  = __fadd_rn(ybase, __fmul_rn((float)r, ystep));
        float yf0 = floorf(fy);
        wyy[k] = fy - yf0;
        int y0i = (int)fminf(fmaxf(yf0, 0.0f), 1023.0f);
        int y1i = (int)fminf(fmaxf(yf0 + 1.0f, 0.0f), 1023.0f);
        bool vy = (fy >= 0.0f) && (fy <= 1023.0f);

        float fx  = __fadd_rn(xbase, __fmul_rn((float)c, xstep));
        float xf0 = floorf(fx);
        wxx[k] = fx - xf0;
        xx0[k] = (int)fminf(fmaxf(xf0, 0.0f), 1023.0f);
        xx1[k] = (int)fminf(fmaxf(xf0 + 1.0f, 0.0f), 1023.0f);
        bool vx = (fx >= 0.0f) && (fx <= 1023.0f);

        vv[k] = vy && vx;
        ra0[k] = ((size_t)(b * IMH + y0i)) * IMW;
        ra1[k] = ((size_t)(b * IMH + y1i)) * IMW;
    }

    // batched gathers (8 loads issued together for MLP)
    float m[2][4];
    #pragma unroll
    for (int k = 0; k < 2; ++k) {
        if (vv[k]) {
            m[k][0] = __ldg(&gt_masks[(ra0[k] + xx0[k]) * NGT + g]);
            m[k][1] = __ldg(&gt_masks[(ra0[k] + xx1[k]) * NGT + g]);
            m[k][2] = __ldg(&gt_masks[(ra1[k] + xx0[k]) * NGT + g]);
            m[k][3] = __ldg(&gt_masks[(ra1[k] + xx1[k]) * NGT + g]);
        }
    }

    #pragma unroll
    for (int k = 0; k < 2; ++k) {
        if (!vv[k]) { mo[k] = 0.0f; continue; }
        float wx = wxx[k], wy = wyy[k];
        float omwx = 1.0f - wx, omwy = 1.0f - wy;
        float top = __fadd_rn(__fmul_rn(m[k][0], omwx), __fmul_rn(m[k][1], wx));
        float bot = __fadd_rn(__fmul_rn(m[k][2], omwx), __fmul_rn(m[k][3], wx));
        float v   = __fadd_rn(__fmul_rn(top, omwy), __fmul_rn(bot, wy));
        mo[k] = rintf(v);   // round half to even
    }
}

// ---------------------------------------------------------------------------
static void compute_keys(Keys* K) {
#if JAX_PARTITIONABLE
    for (int b = 0; b < BB; b++) {
        uint32_t kb0, kb1;
        threefry2x32(0u, 42u, 0u, (uint32_t)b, &kb0, &kb1);
        threefry2x32(kb0, kb1, 0u, 0u, &K->kp0[b], &K->kp1[b]);
        threefry2x32(kb0, kb1, 0u, 1u, &K->kn0[b], &K->kn1[b]);
    }
#else
    uint32_t a0, b0, a1, b1;
    threefry2x32(0u, 42u, 0u, 2u, &a0, &b0);
    threefry2x32(0u, 42u, 1u, 3u, &a1, &b1);
    uint32_t kb[BB][2] = { { a0, a1 }, { b0, b1 } };
    for (int b = 0; b < BB; b++) {
        uint32_t c0, d0, c1, d1;
        threefry2x32(kb[b][0], kb[b][1], 0u, 2u, &c0, &d0);
        threefry2x32(kb[b][0], kb[b][1], 1u, 3u, &c1, &d1);
        K->kp0[b] = c0; K->kp1[b] = c1;
        K->kn0[b] = d0; K->kn1[b] = d1;
    }
#endif
}

extern "C" void kernel_launch(void* const* d_in, const int* in_sizes, int n_in,
                              void* d_out, int out_size)
{
    const float* proposals    = (const float*)d_in[0];
    const int*   gt_class_ids = (const int*)d_in[1];
    const float* gt_boxes     = (const float*)d_in[2];
    const float* gt_masks     = (const float*)d_in[3];
    float* out = (float*)d_out;

    Keys keys;
    compute_keys(&keys);

    dtl_main2<<<BB, 1024>>>(proposals, gt_class_ids, gt_boxes, out, keys);
    const int npix_pairs = (BB * TRAIN * MH * MW) / 2;
    dtl_masks2<<<(npix_pairs + 255) / 256, 256>>>(gt_masks, out);
}